// round 3
// baseline (speedup 1.0000x reference)
#include <cuda_runtime.h>
#include <cstdint>
#include <cstddef>

#define TT 512
#define CC 128
#define LL 80
#define BLANKC 127
#define FEPS 1e-7f
#define FULLM 0xffffffffu
#define DPF 8

// One warp (= one block) per batch element. States split by parity:
//  e_i = alpha[2i]   (blank states, i=0..80): lane l holds e_l, e_{32+l}, e_{64+l}
//  o_i = alpha[2i+1] (label states, i=0..79): lane l holds o_l, o_{32+l}, o_{64+l}
// Blank emission is ONE uniform scalar per row (y[t][127]); label gathers are
// 3 LDGs. Both gather values AND the full-row (softmax-norm) float4 stream are
// prefetched DPF=8 rows ahead in registers, giving ~5KB DRAM bytes in flight
// per warp (Little's law -> near LTS-cap bandwidth). Linear-domain recursion
// with 8-step lagged rescaling; row log-norms via a 5-stage software-pipelined
// shfl butterfly; all accumulators float.
__global__ void __launch_bounds__(32, 1) ctc_kernel(
    const int* __restrict__ lab32,
    const float* __restrict__ ypred,
    float* __restrict__ out)
{
    const int lane = threadIdx.x;
    const int b = blockIdx.x;
    const float* __restrict__ yb = ypred + (size_t)b * (TT * CC);

    // detect label element width (int64 little-endian vs int32)
    int probe = lab32[1] | lab32[3] | lab32[5] | lab32[7]
              | lab32[9] | lab32[11] | lab32[13] | lab32[15];
    const int stride = (probe == 0) ? 2 : 1;
    const int* lb = lab32 + (size_t)b * LL * stride;

    const int i1 = 32 + lane, i2 = 64 + lane;
    const int L0 = lb[lane * stride];
    const int L1 = lb[i1 * stride];
    const bool v2 = (i2 < LL);
    const int L2 = v2 ? lb[i2 * stride] : BLANKC;
    const float al0 = (lane == 0) ? 0.f : ((L0 != lb[(lane - 1) * stride]) ? 1.f : 0.f);
    const float al1 = (L1 != lb[(i1 - 1) * stride]) ? 1.f : 0.f;
    const float al2 = (v2 && (L2 != lb[(i2 - 1) * stride])) ? 1.f : 0.f;

    const float* __restrict__ gB = yb + BLANKC;
    const float* __restrict__ g0 = yb + L0;
    const float* __restrict__ g1 = yb + L1;
    const float* __restrict__ g2 = yb + L2;
    const float* __restrict__ gN = yb + lane * 4;

    // prime DPF-deep pipelines (rows 0..DPF-1): gathers + full-row float4
    float qB[DPF], q0[DPF], q1[DPF], q2[DPF];
    float4 nq[DPF];
#pragma unroll
    for (int r = 0; r < DPF; r++) {
        qB[r] = gB[(size_t)r * CC];
        q0[r] = g0[(size_t)r * CC];
        q1[r] = g1[(size_t)r * CC];
        q2[r] = g2[(size_t)r * CC];
        nq[r] = *(const float4*)(gN + (size_t)r * CC);
    }

    float e0 = 0.f, e1 = 0.f, e2 = 0.f, o0 = 0.f, o1 = 0.f, o2 = 0.f;
    float np0 = 0.f, np1 = 0.f, np2 = 0.f, np3 = 0.f, np4 = 0.f;
    float accN0 = 0.f, accN1 = 0.f, accS = 0.f;
    float rs = 0.f, pend = 0.f, cN = 1.f;
    int t = 0;

#define CTC_STEP(FIRST, U) do {                                                     \
    /* consume slot U (row t), refill with row t+DPF */                             \
    float yB = qB[U] + FEPS;                                                        \
    float y0 = q0[U] + FEPS;                                                        \
    float y1 = q1[U] + FEPS;                                                        \
    float y2 = v2 ? (q2[U] + FEPS) : 0.f;                                           \
    float4 v4 = nq[U];                                                              \
    float loc = (v4.x + v4.y) + (v4.z + v4.w);                                      \
    { int tn = t + DPF;                                                             \
      if (tn < TT) {                                                                \
          qB[U] = gB[(size_t)tn * CC]; q0[U] = g0[(size_t)tn * CC];                 \
          q1[U] = g1[(size_t)tn * CC]; q2[U] = g2[(size_t)tn * CC];                 \
          nq[U] = *(const float4*)(gN + (size_t)tn * CC); } }                       \
    /* norm pipeline: finish row t-5 */                                             \
    if (!(FIRST) || (U) >= 5) {                                                     \
        float fin = np4 + __shfl_xor_sync(FULLM, np4, 1);                           \
        float lg = __logf(fin + (float)CC * FEPS);                                  \
        if (((U) & 1) == 0) accN0 += lg; else accN1 += lg;                          \
    }                                                                               \
    np4 = np3 + __shfl_xor_sync(FULLM, np3, 2);                                     \
    np3 = np2 + __shfl_xor_sync(FULLM, np2, 4);                                     \
    np2 = np1 + __shfl_xor_sync(FULLM, np1, 8);                                     \
    np1 = np0 + __shfl_xor_sync(FULLM, np0, 16);                                    \
    np0 = loc;                                                                      \
    if ((FIRST) && (U) == 0) {                                                      \
        e0 = (lane == 0) ? yB : 0.f;                                                \
        o0 = (lane == 0) ? y0 : 0.f;                                                \
    } else {                                                                        \
        float bb0 = __shfl_sync(FULLM, o0, 31);                                     \
        float bb1 = __shfl_sync(FULLM, o1, 31);                                     \
        float m0 = __shfl_up_sync(FULLM, o0, 1);                                    \
        float m1 = __shfl_up_sync(FULLM, o1, 1);                                    \
        float m2 = __shfl_up_sync(FULLM, o2, 1);                                    \
        if (lane == 0) { m0 = 0.f; m1 = bb0; m2 = bb1; }                            \
        float ne0 = yB * (e0 + m0);                                                 \
        float ne1 = yB * (e1 + m1);                                                 \
        float ne2 = yB * (e2 + m2);                                                 \
        float no0 = y0 * __fmaf_rn(al0, m0, o0 + e0);                               \
        float no1 = y1 * __fmaf_rn(al1, m1, o1 + e1);                               \
        float no2 = y2 * __fmaf_rn(al2, m2, o2 + e2);                               \
        e0 = ne0; e1 = ne1; e2 = ne2; o0 = no0; o1 = no1; o2 = no2;                 \
    }                                                                               \
    /* lagged rescale: one butterfly stage per step, applied at U==7 */             \
    if ((U) == 0)      { rs = ((e0 + e1) + (e2 + o0)) + (o1 + o2); }                \
    else if ((U) == 1) { rs += __shfl_xor_sync(FULLM, rs, 16); }                    \
    else if ((U) == 2) { rs += __shfl_xor_sync(FULLM, rs, 8); }                     \
    else if ((U) == 3) { rs += __shfl_xor_sync(FULLM, rs, 4); }                     \
    else if ((U) == 4) { rs += __shfl_xor_sync(FULLM, rs, 2); }                     \
    else if ((U) == 5) { rs += __shfl_xor_sync(FULLM, rs, 1); }                     \
    else if ((U) == 6) { pend = __logf(rs); cN = __fdividef(1.f, rs); }             \
    else               { e0 *= cN; e1 *= cN; e2 *= cN;                              \
                         o0 *= cN; o1 *= cN; o2 *= cN; accS += pend; }              \
    t++;                                                                            \
} while (0)

    CTC_STEP(1, 0); CTC_STEP(1, 1); CTC_STEP(1, 2); CTC_STEP(1, 3);
    CTC_STEP(1, 4); CTC_STEP(1, 5); CTC_STEP(1, 6); CTC_STEP(1, 7);

#pragma unroll 1
    for (int g = 1; g < TT / 8; g++) {
        CTC_STEP(0, 0); CTC_STEP(0, 1); CTC_STEP(0, 2); CTC_STEP(0, 3);
        CTC_STEP(0, 4); CTC_STEP(0, 5); CTC_STEP(0, 6); CTC_STEP(0, 7);
    }
#undef CTC_STEP

    // drain norm pipeline (rows TT-5 .. TT-1)
#pragma unroll
    for (int d = 0; d < 5; d++) {
        float fin = np4 + __shfl_xor_sync(FULLM, np4, 1);
        float lg = __logf(fin + (float)CC * FEPS);
        if ((d & 1) == 0) accN0 += lg; else accN1 += lg;
        np4 = np3 + __shfl_xor_sync(FULLM, np3, 2);
        np3 = np2 + __shfl_xor_sync(FULLM, np2, 4);
        np2 = np1 + __shfl_xor_sync(FULLM, np1, 8);
        np1 = np0 + __shfl_xor_sync(FULLM, np0, 16);
        np0 = 0.f;
    }

    // tail: states 160 (e_80 = e2@lane16) and 159 (o_79 = o2@lane15)
    float accN = accN0 + accN1;
    float e80 = __shfl_sync(FULLM, e2, 16);
    float o79 = __shfl_sync(FULLM, o2, 15);
    if (lane == 0) {
        out[b] = -(__logf(e80 + o79) + accS - accN);
    }
}

extern "C" void kernel_launch(void* const* d_in, const int* in_sizes, int n_in,
                              void* d_out, int out_size) {
    (void)in_sizes; (void)n_in; (void)out_size;
    const int* labels = (const int*)d_in[0];
    const float* ypred = (const float*)d_in[1];
    float* out = (float*)d_out;
    ctc_kernel<<<512, 32>>>(labels, ypred, out);
}